// round 16
// baseline (speedup 1.0000x reference)
#include <cuda_runtime.h>
#include <math.h>

#define TOTAL_PTS    172032
#define NBLK         1344         // blocks; 128 threads x 1 pt = 128 pts/block
#define BLKS_PER_IMG 168          // 21504 / 128
#define INF_A        1.0e8f
#define NCLS         20
#define LN2_075      0.5198603854199589f     // 0.75 * ln(2)
#define W_THRESH     -0.8472978603872037f    // ln(0.3/0.7)

__device__ float4   g_part[NBLK];
__device__ unsigned g_count = 0;

__device__ __forceinline__ void red3(float& a, float& b, float& c) {
    #pragma unroll
    for (int off = 16; off > 0; off >>= 1) {
        a += __shfl_down_sync(0xffffffffu, a, off);
        b += __shfl_down_sync(0xffffffffu, b, off);
        c += __shfl_down_sync(0xffffffffu, c, off);
    }
}

__device__ __forceinline__ float4 warp_red4(float4 a) {
    #pragma unroll
    for (int off = 16; off > 0; off >>= 1) {
        a.x += __shfl_down_sync(0xffffffffu, a.x, off);
        a.y += __shfl_down_sync(0xffffffffu, a.y, off);
        a.z += __shfl_down_sync(0xffffffffu, a.z, off);
        a.w += __shfl_down_sync(0xffffffffu, a.w, off);
    }
    return a;
}

// Templated ONLY on the prediction-side level Q (compile-time HW for loads).
// Target-side level data stays runtime — the two flattenings disagree per block.
// Writes per-warp partial to sw[wid] (lane 0, all paths).
template<int Q>
__device__ __forceinline__ void body(
    const int tid, const int bid,
    const int b_img, const int lv_t, const float lmin, const float lmax,
    const float x, const float y,
    const float ymin_blk, const float ymax_blk,
    const float* __restrict__ cb, const float* __restrict__ rb, const float* __restrict__ ob,
    const float* __restrict__ boxes, const int* __restrict__ labels,
    float4* sbox, float* sarea, int* slab, int* s_n, float4* sw)
{
    constexpr int HW   = (Q == 0) ? 16384 : (Q == 1) ? 4096 : 1024;
    constexpr int QSH  = (Q == 0) ? 14 : (Q == 1) ? 12 : 10;      // log2(HW)
    constexpr int JOFF = (Q == 0) ? 0 : (Q == 1) ? 131072 : 163840;

    const int wid  = tid >> 5;
    const int lane = tid & 31;

    // ---- prediction-side decode: jl >= 0 guaranteed by dispatch on j0 ----
    const int jl  = (bid << 7) - JOFF;
    const int b_f = jl >> QSH;
    const int pix = (jl & (HW - 1)) + tid;

    const float* cptr = cb + (size_t)(b_f * NCLS) * HW + pix;

    // ---- STAGE 1: prefetch only cls planes 0..3 ----
    float v[NCLS];
    #pragma unroll
    for (int c = 0; c < 4; c++)
        v[c] = cptr[c * HW];

    // ---- box cull + stable compaction (warp 0; lv_t warp-uniform).
    //      128-pt blocks: level 0 spans ONE row -> exact y cull. ----
    if (tid < 32) {
        const float4 bb = reinterpret_cast<const float4*>(boxes)[b_img * 32 + tid];
        const float bw = bb.z - bb.x, bh = bb.w - bb.y;
        bool keep = (bb.y < ymax_blk) & (bb.w > ymin_blk);   // y-overlap
        if (lv_t == 0)      keep = keep & (bw <= 128.0f) & (bh <= 128.0f);
        else if (lv_t == 1) keep = keep & ((bw >= 64.0f)  | (bh >= 64.0f));
        else                keep = keep & ((bw >= 128.0f) | (bh >= 128.0f));
        const unsigned m = __ballot_sync(0xffffffffu, keep);
        if (keep) {
            const int idx = __popc(m & ((1u << tid) - 1u));   // stable order
            sbox[idx]  = bb;
            sarea[idx] = bw * bh;
            slab[idx]  = labels[b_img * 32 + tid];
        }
        if (tid == 0) *s_n = __popc(m);
    }
    __syncthreads();
    const int nbox = *s_n;

    // ---- box assignment over compacted survivors ----
    float best = INF_A;
    int   bi   = 0;
    for (int m = 0; m < nbox; m++) {
        const float4 bb = sbox[m];
        const float l  = x - bb.x;
        const float t  = y - bb.y;
        const float r  = bb.z - x;
        const float bo = bb.w - y;
        const float mn = fminf(fminf(l, t), fminf(r, bo));
        const float mx = fmaxf(fmaxf(l, t), fmaxf(r, bo));
        const bool ok = (mn > 0.0f) & (mx >= lmin) & (mx <= lmax);
        const float a = sarea[m];
        if (ok & (a < best)) { best = a; bi = m; }
    }
    const bool pos   = best < INF_A;
    const int  label = pos ? slab[bi] : -1;
    const unsigned posb = __ballot_sync(0xffffffffu, pos);

    // ---- ignore-weight early exit (bit-exact):
    //      A negative point contributes ONLY if max logit <= ln(3/7).
    //      After 4 planes a neg lane is decided with P = 1 - 0.2^4 = 0.9984.
    //      A fully-exited warp contributes EXACTLY (0,0,0,0). ----
    const float m4 = fmaxf(fmaxf(v[0], v[1]), fmaxf(v[2], v[3]));
    const bool need = pos | (m4 <= W_THRESH);

    if (!__any_sync(0xffffffffu, need)) {
        if (lane == 0) sw[wid] = make_float4(0.f, 0.f, 0.f, 0.f);
        return;
    }

    // ---- STAGE 2: batch ALL remaining loads (16 cls planes + reg/ctr) in one
    //      burst for max MLP; focal on planes 0..3 overlaps their latency. ----
    #pragma unroll
    for (int c = 4; c < NCLS; c++)
        v[c] = cptr[c * HW];

    const float* rp = rb + (size_t)(b_f * 4) * HW + pix;
    const float* op = ob + (size_t)b_f * HW + pix;
    float rg[4] = {0.f, 0.f, 0.f, 0.f};
    float oc    = 0.f;
    if (pos) {
        #pragma unroll
        for (int k = 0; k < 4; k++)
            rg[k] = rp[k * HW];
        oc = *op;
    }

    // focal partial over resident planes 0..3 (overlaps stage-2 load latency)
    float fsum = 0.0f;
    #pragma unroll
    for (int c = 0; c < 4; c++) {
        const float xx = v[c];
        const float E  = __expf(xx);
        const float u  = 1.0f + E;
        const float rc = __fdividef(1.0f, u);
        const float pp = E * rc;
        fsum += __log2f(u) * (pp * pp);
    }

    float maxx = m4;
    #pragma unroll
    for (int c = 4; c < NCLS; c++) maxx = fmaxf(maxx, v[c]);

    float4 acc = make_float4(0.f, 0.f, 0.f, 0.f);
    if (pos | (maxx <= W_THRESH)) {
        #pragma unroll
        for (int c = 4; c < NCLS; c++) {
            const float xx = v[c];
            const float E  = __expf(xx);
            const float u  = 1.0f + E;
            const float rc = __fdividef(1.0f, u);
            const float pp = E * rc;
            fsum += __log2f(u) * (pp * pp);
        }
        float f = fsum * LN2_075;
        if (pos) {
            // focal correction for the hit class (reload logit; cache hit)
            const float xl = cptr[label * HW];
            const float E  = __expf(xl);
            const float u  = 1.0f + E;
            const float rc = __fdividef(1.0f, u);
            const float pp = E * rc;
            const float sp = __logf(u);
            f += 0.25f * (sp - xl) * rc * rc - 0.75f * sp * pp * pp;
        }
        acc.x = f;
    }

    // ---- pos-only losses ----
    if (pos) {
        // targets for winning box
        const float4 wb = sbox[bi];
        const float tl = x - wb.x, tt = y - wb.y, tr = wb.z - x, tb = wb.w - y;
        const float lrmin = fminf(tl, tr), lrmax = fmaxf(tl, tr);
        const float tbmin = fminf(tt, tb), tbmax = fmaxf(tt, tb);
        const float ratio = __fdividef(lrmin, fmaxf(lrmax, 1e-12f)) *
                            __fdividef(tbmin, fmaxf(tbmax, 1e-12f));
        const float ctr_t = sqrtf(fmaxf(ratio, 0.0f));

        // GIoU
        const float pl  = rg[0];
        const float pt2 = rg[1];
        const float pr  = rg[2];
        const float pb  = rg[3];
        const float t_area = (tl + tr) * (tt + tb);
        const float p_area = (pl + pr) * (pt2 + pb);
        const float w_i = fminf(pl, tl) + fminf(pr, tr);
        const float h_i = fminf(pb, tb) + fminf(pt2, tt);
        const float a_i = w_i * h_i;
        const float a_u = t_area + p_area - a_i;
        const float iou = __fdividef(a_i + 1.0f, a_u + 1.0f);
        const float gw  = fmaxf(pl, tl) + fmaxf(pr, tr);
        const float gh  = fmaxf(pb, tb) + fmaxf(pt2, tt);
        const float ac  = gw * gh;
        acc.y = (1.0f - (iou - __fdividef(ac - a_u, ac))) * ctr_t;

        // centerness BCE
        const float e2 = __expf(-fabsf(oc));
        acc.z = fmaxf(oc, 0.0f) + __logf(1.0f + e2) - oc * ctr_t;
    }

    // ---- 3-channel warp reduction; pos-count via popc(ballot) ----
    red3(acc.x, acc.y, acc.z);
    if (lane == 0) sw[wid] = make_float4(acc.x, acc.y, acc.z, (float)__popc(posb));
}

__global__ __launch_bounds__(128) void k_fused(
    const float* __restrict__ cls0, const float* __restrict__ cls1, const float* __restrict__ cls2,
    const float* __restrict__ reg0, const float* __restrict__ reg1, const float* __restrict__ reg2,
    const float* __restrict__ ctr0, const float* __restrict__ ctr1, const float* __restrict__ ctr2,
    const float* __restrict__ boxes, const int* __restrict__ labels,
    float* __restrict__ out)
{
    __shared__ float4 sbox[32];
    __shared__ float  sarea[32];
    __shared__ int    slab[32];
    __shared__ int    s_n;
    __shared__ float4 sw[4];
    __shared__ bool   s_last;

    const int tid = threadIdx.x;
    const int bid = blockIdx.x;

    // ---- target-side (batch-major) decode — INDEPENDENT of prediction side ----
    const int b_img = bid / BLKS_PER_IMG;
    const int pblk  = (bid - b_img * BLKS_PER_IMG) << 7;   // 128 pts/block

    int lv_t, base, Wsh; float s, lmin, lmax;
    if (pblk < 16384)      { lv_t = 0; base = 0;     Wsh = 7; s = 4.0f;  lmin = -1.0f;  lmax = 64.0f;  }
    else if (pblk < 20480) { lv_t = 1; base = 16384; Wsh = 6; s = 8.0f;  lmin = 64.0f;  lmax = 128.0f; }
    else                   { lv_t = 2; base = 20480; Wsh = 5; s = 16.0f; lmin = 128.0f; lmax = INF_A;  }

    const int p0 = pblk + tid - base;
    const int hh = p0 >> Wsh;
    const int ww = p0 & ((1 << Wsh) - 1);
    const float x = ww * s + 0.5f * s;
    const float y = hh * s + 0.5f * s;

    const int lo_blk = pblk - base;
    const float ymin_blk = (float)(lo_blk >> Wsh) * s + 0.5f * s;
    const float ymax_blk = (float)((lo_blk + 127) >> Wsh) * s + 0.5f * s;

    // ---- dispatch on PREDICTION-side level (j0 thresholds) ----
    const int j0 = bid << 7;
    if (j0 < 131072)
        body<0>(tid, bid, b_img, lv_t, lmin, lmax, x, y, ymin_blk, ymax_blk,
                cls0, reg0, ctr0, boxes, labels, sbox, sarea, slab, &s_n, sw);
    else if (j0 < 163840)
        body<1>(tid, bid, b_img, lv_t, lmin, lmax, x, y, ymin_blk, ymax_blk,
                cls1, reg1, ctr1, boxes, labels, sbox, sarea, slab, &s_n, sw);
    else
        body<2>(tid, bid, b_img, lv_t, lmin, lmax, x, y, ymin_blk, ymax_blk,
                cls2, reg2, ctr2, boxes, labels, sbox, sarea, slab, &s_n, sw);

    // ---- block reduction: sum 4 per-warp partials ----
    __syncthreads();
    if (tid == 0) {
        float4 a = sw[0];
        #pragma unroll
        for (int k = 1; k < 4; k++) {
            a.x += sw[k].x; a.y += sw[k].y; a.z += sw[k].z; a.w += sw[k].w;
        }
        g_part[bid] = a;
        __threadfence();
        const unsigned old = atomicAdd(&g_count, 1u);
        s_last = (old == (unsigned)(gridDim.x - 1));
    }
    __syncthreads();
    if (!s_last) return;
    __threadfence();

    // ---- last block finalizes ----
    float4 a = make_float4(0.f, 0.f, 0.f, 0.f);
    for (int i = tid; i < NBLK; i += 128) {
        const float4* pp = &g_part[i];
        float4 vv;
        asm volatile("ld.global.cg.v4.f32 {%0,%1,%2,%3}, [%4];"
                     : "=f"(vv.x), "=f"(vv.y), "=f"(vv.z), "=f"(vv.w) : "l"(pp));
        a.x += vv.x; a.y += vv.y; a.z += vv.z; a.w += vv.w;
    }
    a = warp_red4(a);
    if ((tid & 31) == 0) sw[tid >> 5] = a;
    __syncthreads();
    if (tid == 0) {
        float sx = 0.f, sy = 0.f, sz = 0.f, np = 0.f;
        #pragma unroll
        for (int k = 0; k < 4; k++) { sx += sw[k].x; sy += sw[k].y; sz += sw[k].z; np += sw[k].w; }
        const float inv = __fdividef(1.0f, fmaxf(np, 1.0f));
        out[0] = sx * inv;
        out[1] = sy * inv;
        out[2] = sz * inv;
        g_count = 0;   // reset for next graph replay
    }
}

extern "C" void kernel_launch(void* const* d_in, const int* in_sizes, int n_in,
                              void* d_out, int out_size) {
    const float *cls0, *cls1, *cls2, *reg0, *reg1, *reg2, *ctr0, *ctr1, *ctr2;
    if (in_sizes[1] == 655360) {   // reference-signature order
        cls0 = (const float*)d_in[0]; cls1 = (const float*)d_in[1]; cls2 = (const float*)d_in[2];
        reg0 = (const float*)d_in[3]; reg1 = (const float*)d_in[4]; reg2 = (const float*)d_in[5];
        ctr0 = (const float*)d_in[6]; ctr1 = (const float*)d_in[7]; ctr2 = (const float*)d_in[8];
    } else {                       // setup_inputs dict order
        cls0 = (const float*)d_in[0]; reg0 = (const float*)d_in[1]; ctr0 = (const float*)d_in[2];
        cls1 = (const float*)d_in[3]; reg1 = (const float*)d_in[4]; ctr1 = (const float*)d_in[5];
        cls2 = (const float*)d_in[6]; reg2 = (const float*)d_in[7]; ctr2 = (const float*)d_in[8];
    }
    const float* boxes  = (const float*)d_in[9];
    const int*   labels = (const int*)d_in[10];

    k_fused<<<NBLK, 128>>>(cls0, cls1, cls2, reg0, reg1, reg2,
                           ctr0, ctr1, ctr2, boxes, labels, (float*)d_out);
}

// round 17
// speedup vs baseline: 1.3072x; 1.3072x over previous
#include <cuda_runtime.h>
#include <math.h>

#define TOTAL_PTS    172032
#define NBLK         672          // blocks; 256 threads x 1 pt = 256 pts/block
#define BLKS_PER_IMG 84           // 21504 / 256
#define INF_A        1.0e8f
#define NCLS         20
#define LN2_075      0.5198603854199589f     // 0.75 * ln(2)
#define W_THRESH     -0.8472978603872037f    // ln(0.3/0.7)

__device__ float4   g_part[NBLK];
__device__ unsigned g_count = 0;

__device__ __forceinline__ void red3(float& a, float& b, float& c) {
    #pragma unroll
    for (int off = 16; off > 0; off >>= 1) {
        a += __shfl_down_sync(0xffffffffu, a, off);
        b += __shfl_down_sync(0xffffffffu, b, off);
        c += __shfl_down_sync(0xffffffffu, c, off);
    }
}

__device__ __forceinline__ float4 warp_red4(float4 a) {
    #pragma unroll
    for (int off = 16; off > 0; off >>= 1) {
        a.x += __shfl_down_sync(0xffffffffu, a.x, off);
        a.y += __shfl_down_sync(0xffffffffu, a.y, off);
        a.z += __shfl_down_sync(0xffffffffu, a.z, off);
        a.w += __shfl_down_sync(0xffffffffu, a.w, off);
    }
    return a;
}

// Templated ONLY on the prediction-side level Q (compile-time HW for loads).
// Target-side level data stays runtime — the two flattenings disagree per block.
// Writes per-warp partial to sw[wid] (lane 0, all paths).
template<int Q>
__device__ __forceinline__ void body(
    const int tid, const int bid,
    const int b_img, const int lv_t, const float lmin, const float lmax,
    const float x, const float y,
    const float ymin_blk, const float ymax_blk,
    const float* __restrict__ cb, const float* __restrict__ rb, const float* __restrict__ ob,
    const float* __restrict__ boxes, const int* __restrict__ labels,
    float4* sbox, float* sarea, int* slab, int* s_n, float4* sw)
{
    constexpr int HW   = (Q == 0) ? 16384 : (Q == 1) ? 4096 : 1024;
    constexpr int QSH  = (Q == 0) ? 14 : (Q == 1) ? 12 : 10;      // log2(HW)
    constexpr int JOFF = (Q == 0) ? 0 : (Q == 1) ? 131072 : 163840;

    const int wid  = tid >> 5;
    const int lane = tid & 31;

    // ---- prediction-side decode: jl >= 0 guaranteed by dispatch on j0 ----
    const int jl  = (bid << 8) - JOFF;
    const int b_f = jl >> QSH;
    const int pix = (jl & (HW - 1)) + tid;

    const float* cptr = cb + (size_t)(b_f * NCLS) * HW + pix;

    // ---- warp 0: issue boxes+labels FIRST (L1tex queue completes roughly in
    //      issue order; the cull — and thus the block barrier — depends on
    //      these, while the cls planes aren't needed until after argmin). ----
    float4 bb_me; int lb_me = 0;
    if (tid < 32) {
        bb_me = reinterpret_cast<const float4*>(boxes)[b_img * 32 + tid];
        lb_me = labels[b_img * 32 + tid];
    }

    // ---- STAGE 1: prefetch only cls planes 0..3 ----
    float v[NCLS];
    #pragma unroll
    for (int c = 0; c < 4; c++)
        v[c] = cptr[c * HW];

    // ---- box cull + stable compaction (warp 0; lv_t warp-uniform) ----
    if (tid < 32) {
        const float bw = bb_me.z - bb_me.x, bh = bb_me.w - bb_me.y;
        bool keep = (bb_me.y < ymax_blk) & (bb_me.w > ymin_blk);   // y-overlap
        if (lv_t == 0)      keep = keep & (bw <= 128.0f) & (bh <= 128.0f);
        else if (lv_t == 1) keep = keep & ((bw >= 64.0f)  | (bh >= 64.0f));
        else                keep = keep & ((bw >= 128.0f) | (bh >= 128.0f));
        const unsigned m = __ballot_sync(0xffffffffu, keep);
        if (keep) {
            const int idx = __popc(m & ((1u << tid) - 1u));   // stable order
            sbox[idx]  = bb_me;
            sarea[idx] = bw * bh;
            slab[idx]  = lb_me;
        }
        if (tid == 0) *s_n = __popc(m);
    }
    __syncthreads();
    const int nbox = *s_n;

    // ---- box assignment over compacted survivors ----
    float best = INF_A;
    int   bi   = 0;
    for (int m = 0; m < nbox; m++) {
        const float4 bb = sbox[m];
        const float l  = x - bb.x;
        const float t  = y - bb.y;
        const float r  = bb.z - x;
        const float bo = bb.w - y;
        const float mn = fminf(fminf(l, t), fminf(r, bo));
        const float mx = fmaxf(fmaxf(l, t), fmaxf(r, bo));
        const bool ok = (mn > 0.0f) & (mx >= lmin) & (mx <= lmax);
        const float a = sarea[m];
        if (ok & (a < best)) { best = a; bi = m; }
    }
    const bool pos   = best < INF_A;
    const int  label = pos ? slab[bi] : -1;
    const unsigned posb = __ballot_sync(0xffffffffu, pos);

    // ---- ignore-weight early exit (bit-exact):
    //      A negative point contributes ONLY if max logit <= ln(3/7).
    //      After 4 planes a neg lane is decided with P = 1 - 0.2^4 = 0.9984.
    //      A fully-exited warp contributes EXACTLY (0,0,0,0): skip loads,
    //      focal, AND the warp reduction — just write zeros. ----
    const float m4 = fmaxf(fmaxf(v[0], v[1]), fmaxf(v[2], v[3]));
    const bool need = pos | (m4 <= W_THRESH);

    if (!__any_sync(0xffffffffu, need)) {
        if (lane == 0) sw[wid] = make_float4(0.f, 0.f, 0.f, 0.f);
        return;
    }

    // ---- STAGE 2: batch ALL remaining loads (16 cls planes + reg/ctr) in one
    //      burst for max MLP; focal on planes 0..3 overlaps their latency. ----
    #pragma unroll
    for (int c = 4; c < NCLS; c++)
        v[c] = cptr[c * HW];

    const float* rp = rb + (size_t)(b_f * 4) * HW + pix;
    const float* op = ob + (size_t)b_f * HW + pix;
    float rg[4] = {0.f, 0.f, 0.f, 0.f};
    float oc    = 0.f;
    if (pos) {
        #pragma unroll
        for (int k = 0; k < 4; k++)
            rg[k] = rp[k * HW];
        oc = *op;
    }

    // focal partial over resident planes 0..3 (overlaps stage-2 load latency)
    float fsum = 0.0f;
    #pragma unroll
    for (int c = 0; c < 4; c++) {
        const float xx = v[c];
        const float E  = __expf(xx);
        const float u  = 1.0f + E;
        const float rc = __fdividef(1.0f, u);
        const float pp = E * rc;
        fsum += __log2f(u) * (pp * pp);
    }

    float maxx = m4;
    #pragma unroll
    for (int c = 4; c < NCLS; c++) maxx = fmaxf(maxx, v[c]);

    float4 acc = make_float4(0.f, 0.f, 0.f, 0.f);
    if (pos | (maxx <= W_THRESH)) {
        #pragma unroll
        for (int c = 4; c < NCLS; c++) {
            const float xx = v[c];
            const float E  = __expf(xx);
            const float u  = 1.0f + E;
            const float rc = __fdividef(1.0f, u);
            const float pp = E * rc;
            fsum += __log2f(u) * (pp * pp);
        }
        float f = fsum * LN2_075;
        if (pos) {
            // focal correction for the hit class (reload logit; cache hit)
            const float xl = cptr[label * HW];
            const float E  = __expf(xl);
            const float u  = 1.0f + E;
            const float rc = __fdividef(1.0f, u);
            const float pp = E * rc;
            const float sp = __logf(u);
            f += 0.25f * (sp - xl) * rc * rc - 0.75f * sp * pp * pp;
        }
        acc.x = f;
    }

    // ---- pos-only losses ----
    if (pos) {
        // targets for winning box
        const float4 wb = sbox[bi];
        const float tl = x - wb.x, tt = y - wb.y, tr = wb.z - x, tb = wb.w - y;
        const float lrmin = fminf(tl, tr), lrmax = fmaxf(tl, tr);
        const float tbmin = fminf(tt, tb), tbmax = fmaxf(tt, tb);
        const float ratio = __fdividef(lrmin, fmaxf(lrmax, 1e-12f)) *
                            __fdividef(tbmin, fmaxf(tbmax, 1e-12f));
        const float ctr_t = sqrtf(fmaxf(ratio, 0.0f));

        // GIoU
        const float pl  = rg[0];
        const float pt2 = rg[1];
        const float pr  = rg[2];
        const float pb  = rg[3];
        const float t_area = (tl + tr) * (tt + tb);
        const float p_area = (pl + pr) * (pt2 + pb);
        const float w_i = fminf(pl, tl) + fminf(pr, tr);
        const float h_i = fminf(pb, tb) + fminf(pt2, tt);
        const float a_i = w_i * h_i;
        const float a_u = t_area + p_area - a_i;
        const float iou = __fdividef(a_i + 1.0f, a_u + 1.0f);
        const float gw  = fmaxf(pl, tl) + fmaxf(pr, tr);
        const float gh  = fmaxf(pb, tb) + fmaxf(pt2, tt);
        const float ac  = gw * gh;
        acc.y = (1.0f - (iou - __fdividef(ac - a_u, ac))) * ctr_t;

        // centerness BCE
        const float e2 = __expf(-fabsf(oc));
        acc.z = fmaxf(oc, 0.0f) + __logf(1.0f + e2) - oc * ctr_t;
    }

    // ---- 3-channel warp reduction; pos-count via popc(ballot) ----
    red3(acc.x, acc.y, acc.z);
    if (lane == 0) sw[wid] = make_float4(acc.x, acc.y, acc.z, (float)__popc(posb));
}

__global__ __launch_bounds__(256) void k_fused(
    const float* __restrict__ cls0, const float* __restrict__ cls1, const float* __restrict__ cls2,
    const float* __restrict__ reg0, const float* __restrict__ reg1, const float* __restrict__ reg2,
    const float* __restrict__ ctr0, const float* __restrict__ ctr1, const float* __restrict__ ctr2,
    const float* __restrict__ boxes, const int* __restrict__ labels,
    float* __restrict__ out)
{
    __shared__ float4 sbox[32];
    __shared__ float  sarea[32];
    __shared__ int    slab[32];
    __shared__ int    s_n;
    __shared__ float4 sw[8];
    __shared__ bool   s_last;

    const int tid = threadIdx.x;
    const int bid = blockIdx.x;

    // ---- target-side (batch-major) decode — INDEPENDENT of prediction side ----
    const int b_img = bid / BLKS_PER_IMG;
    const int pblk  = (bid - b_img * BLKS_PER_IMG) << 8;

    int lv_t, base, Wsh; float s, lmin, lmax;
    if (pblk < 16384)      { lv_t = 0; base = 0;     Wsh = 7; s = 4.0f;  lmin = -1.0f;  lmax = 64.0f;  }
    else if (pblk < 20480) { lv_t = 1; base = 16384; Wsh = 6; s = 8.0f;  lmin = 64.0f;  lmax = 128.0f; }
    else                   { lv_t = 2; base = 20480; Wsh = 5; s = 16.0f; lmin = 128.0f; lmax = INF_A;  }

    const int p0 = pblk + tid - base;
    const int hh = p0 >> Wsh;
    const int ww = p0 & ((1 << Wsh) - 1);
    const float x = ww * s + 0.5f * s;
    const float y = hh * s + 0.5f * s;

    const int lo_blk = pblk - base;
    const float ymin_blk = (float)(lo_blk >> Wsh) * s + 0.5f * s;
    const float ymax_blk = (float)((lo_blk + 255) >> Wsh) * s + 0.5f * s;

    // ---- dispatch on PREDICTION-side level (j0 thresholds) ----
    const int j0 = bid << 8;
    if (j0 < 131072)
        body<0>(tid, bid, b_img, lv_t, lmin, lmax, x, y, ymin_blk, ymax_blk,
                cls0, reg0, ctr0, boxes, labels, sbox, sarea, slab, &s_n, sw);
    else if (j0 < 163840)
        body<1>(tid, bid, b_img, lv_t, lmin, lmax, x, y, ymin_blk, ymax_blk,
                cls1, reg1, ctr1, boxes, labels, sbox, sarea, slab, &s_n, sw);
    else
        body<2>(tid, bid, b_img, lv_t, lmin, lmax, x, y, ymin_blk, ymax_blk,
                cls2, reg2, ctr2, boxes, labels, sbox, sarea, slab, &s_n, sw);

    // ---- block reduction: sum 8 per-warp partials ----
    __syncthreads();
    if (tid == 0) {
        float4 a = sw[0];
        #pragma unroll
        for (int k = 1; k < 8; k++) {
            a.x += sw[k].x; a.y += sw[k].y; a.z += sw[k].z; a.w += sw[k].w;
        }
        g_part[bid] = a;
        __threadfence();
        const unsigned old = atomicAdd(&g_count, 1u);
        s_last = (old == (unsigned)(gridDim.x - 1));
    }
    __syncthreads();
    if (!s_last) return;
    __threadfence();

    // ---- last block finalizes ----
    float4 a = make_float4(0.f, 0.f, 0.f, 0.f);
    for (int i = tid; i < NBLK; i += 256) {
        const float4* pp = &g_part[i];
        float4 vv;
        asm volatile("ld.global.cg.v4.f32 {%0,%1,%2,%3}, [%4];"
                     : "=f"(vv.x), "=f"(vv.y), "=f"(vv.z), "=f"(vv.w) : "l"(pp));
        a.x += vv.x; a.y += vv.y; a.z += vv.z; a.w += vv.w;
    }
    a = warp_red4(a);
    if ((tid & 31) == 0) sw[tid >> 5] = a;
    __syncthreads();
    if (tid == 0) {
        float sx = 0.f, sy = 0.f, sz = 0.f, np = 0.f;
        #pragma unroll
        for (int k = 0; k < 8; k++) { sx += sw[k].x; sy += sw[k].y; sz += sw[k].z; np += sw[k].w; }
        const float inv = __fdividef(1.0f, fmaxf(np, 1.0f));
        out[0] = sx * inv;
        out[1] = sy * inv;
        out[2] = sz * inv;
        g_count = 0;   // reset for next graph replay
    }
}

extern "C" void kernel_launch(void* const* d_in, const int* in_sizes, int n_in,
                              void* d_out, int out_size) {
    const float *cls0, *cls1, *cls2, *reg0, *reg1, *reg2, *ctr0, *ctr1, *ctr2;
    if (in_sizes[1] == 655360) {   // reference-signature order
        cls0 = (const float*)d_in[0]; cls1 = (const float*)d_in[1]; cls2 = (const float*)d_in[2];
        reg0 = (const float*)d_in[3]; reg1 = (const float*)d_in[4]; reg2 = (const float*)d_in[5];
        ctr0 = (const float*)d_in[6]; ctr1 = (const float*)d_in[7]; ctr2 = (const float*)d_in[8];
    } else {                       // setup_inputs dict order
        cls0 = (const float*)d_in[0]; reg0 = (const float*)d_in[1]; ctr0 = (const float*)d_in[2];
        cls1 = (const float*)d_in[3]; reg1 = (const float*)d_in[4]; ctr1 = (const float*)d_in[5];
        cls2 = (const float*)d_in[6]; reg2 = (const float*)d_in[7]; ctr2 = (const float*)d_in[8];
    }
    const float* boxes  = (const float*)d_in[9];
    const int*   labels = (const int*)d_in[10];

    k_fused<<<NBLK, 256>>>(cls0, cls1, cls2, reg0, reg1, reg2,
                           ctr0, ctr1, ctr2, boxes, labels, (float*)d_out);
}